// round 4
// baseline (speedup 1.0000x reference)
#include <cuda_runtime.h>
#include <cuda_bf16.h>
#include <cstdint>

// Problem constants (match reference)
#define NUM_LEVELS   16
#define LEVEL_DIM    2
#define BASE_RES     16
#define N_POINTS     524288
#define N_ENTRIES    524309u        // prime hashmap size
#define PS1          19349663ll     // second spatial-hash prime
#define START_HASH   6              // levels >= 6 use spatial hash

// Per-level base offsets into the table (cumulative entry counts)
__device__ __constant__ int LEVEL_OFF[NUM_LEVELS] = {
    0, 289, 1378, 5603, 22244, 88293, 351462,
    875771, 1400080, 1924389, 2448698, 2973007,
    3497316, 4021625, 4545934, 5070243
};

__global__ __launch_bounds__(256)
void plane_encode_kernel(const float* __restrict__ x,
                         const float* __restrict__ data,
                         float* __restrict__ out)
{
    const int t = blockIdx.x * blockDim.x + threadIdx.x;
    const int n = t >> 4;        // point index
    const int l = t & 15;        // level index (lanes 0..15 = one point)
    if (n >= N_POINTS) return;

    // Broadcast within the 16-lane group; coalesced across the warp.
    const float x0 = __ldg(&x[2 * n + 0]);
    const float x1 = __ldg(&x[2 * n + 1]);

    const int   res   = BASE_RES << l;
    const float scale = (float)res;

    const float fx0 = x0 * scale;
    const float fx1 = x1 * scale;

    // Corner integer coords — MUST replicate reference: trunc(fx + corner) in fp32
    const int i0a = (int)fx0;
    const int i0b = (int)(fx0 + 1.0f);
    const int i1a = (int)fx1;
    const int i1b = (int)(fx1 + 1.0f);

    // Fractional part relative to corner (0,0)
    const float f0 = fx0 - (float)i0a;
    const float f1 = fx1 - (float)i1a;

    const float g0 = 1.0f - f0;
    const float g1 = 1.0f - f1;
    // corner order (c0,c1): (0,0) (0,1) (1,0) (1,1)
    const float w00 = g0 * g1;
    const float w01 = g0 * f1;
    const float w10 = f0 * g1;
    const float w11 = f0 * f1;

    unsigned idx00, idx01, idx10, idx11;
    if (l < START_HASH) {
        // dense grid: ix0 * (res+1) + ix1
        const int S = res + 1;
        idx00 = (unsigned)(i0a * S + i1a);
        idx01 = (unsigned)(i0a * S + i1b);
        idx10 = (unsigned)(i0b * S + i1a);
        idx11 = (unsigned)(i0b * S + i1b);
    } else {
        // spatial hash: (ix0 ^ (ix1 * PS1)) % N_ENTRIES  (64-bit, then mod prime)
        const unsigned long long ha = (unsigned long long)((long long)i1a * PS1);
        const unsigned long long hb = (unsigned long long)((long long)i1b * PS1);
        const unsigned long long a0 = (unsigned long long)(long long)i0a;
        const unsigned long long b0 = (unsigned long long)(long long)i0b;
        idx00 = (unsigned)((a0 ^ ha) % N_ENTRIES);
        idx01 = (unsigned)((a0 ^ hb) % N_ENTRIES);
        idx10 = (unsigned)((b0 ^ ha) % N_ENTRIES);
        idx11 = (unsigned)((b0 ^ hb) % N_ENTRIES);
    }

    const int base = LEVEL_OFF[l];
    const float2* __restrict__ tab = (const float2*)data;

    // Issue all 4 gathers back-to-back for MLP=4 per thread (L2 hits, ~234 cyc)
    const float2 v00 = __ldg(&tab[base + (int)idx00]);
    const float2 v01 = __ldg(&tab[base + (int)idx01]);
    const float2 v10 = __ldg(&tab[base + (int)idx10]);
    const float2 v11 = __ldg(&tab[base + (int)idx11]);

    float2 r;
    r.x = w00 * v00.x + w01 * v01.x + w10 * v10.x + w11 * v11.x;
    r.y = w00 * v00.y + w01 * v01.y + w10 * v10.y + w11 * v11.y;

    // 16 lanes of one point write its contiguous 128B output row.
    // Streaming store: keep the 67MB output from evicting the 45MB table in L2.
    __stcs((float2*)(out + (size_t)n * (NUM_LEVELS * LEVEL_DIM)) + l, r);
}

extern "C" void kernel_launch(void* const* d_in, const int* in_sizes, int n_in,
                              void* d_out, int out_size)
{
    const float* x    = (const float*)d_in[0];
    const float* data = (const float*)d_in[1];
    float*       out  = (float*)d_out;

    const int total   = N_POINTS * NUM_LEVELS;   // 8,388,608 threads
    const int threads = 256;
    const int blocks  = (total + threads - 1) / threads;
    plane_encode_kernel<<<blocks, threads>>>(x, data, out);
}